// round 2
// baseline (speedup 1.0000x reference)
#include <cuda_runtime.h>
#include <cstdint>
#include <math.h>

#define NTOK 16384
#define SEQ_MASK 4095
#define DM 1024
#define BM 128
#define BN 128
#define BK 16
#define AST 20    // BK + 4 pad  (A stored [m][k])
#define BST 136   // BN + 8 pad  (B stored [k][n]) -> conflict-free b-frag LDS

// Scratch (allocation-free rule: __device__ globals)
__device__ float g_Q[(size_t)NTOK * DM];
__device__ float g_K[(size_t)NTOK * DM];
__device__ float g_V[(size_t)NTOK * DM];
__device__ float g_cos[4096 * 32];
__device__ float g_sin[4096 * 32];

__device__ __forceinline__ uint32_t to_tf32(float x) {
    uint32_t u;
    asm("cvt.rna.tf32.f32 %0, %1;" : "=r"(u) : "f"(x));
    return u;
}

// Precompute RoPE cos/sin in fp64 (exact-enough angles for s up to 4095)
__global__ void rope_table_kernel() {
    int t = blockIdx.x * blockDim.x + threadIdx.x;
    if (t >= 4096 * 32) return;
    int s = t >> 5, k = t & 31;
    double freq = exp((double)(-2 * k) * (log(10000.0) / 1024.0));
    double ang = (double)s * freq;
    g_cos[t] = (float)cos(ang);
    g_sin[t] = (float)sin(ang);
}

// C[M,N] = X[M,K] @ W[K,N] + bias, tf32 tensor cores, fp32 accumulate.
__global__ __launch_bounds__(256, 2)
void gemm_kernel(const float* __restrict__ X, const float* __restrict__ W,
                 const float* __restrict__ bias, float* __restrict__ out) {
    __shared__ uint32_t As[2][BM][AST];  // tf32 bits, [m][k]
    __shared__ uint32_t Bs[2][BK][BST];  // tf32 bits, [k][n]

    int tid = threadIdx.x;
    int lane = tid & 31;
    int warp = tid >> 5;
    int wm = (warp >> 2) * 64;   // warp tile 64x32
    int wn = (warp & 3) * 32;
    int bm = blockIdx.y * BM;
    int bn = blockIdx.x * BN;

    float acc[4][4][4];
#pragma unroll
    for (int i = 0; i < 4; i++)
#pragma unroll
        for (int j = 0; j < 4; j++)
#pragma unroll
            for (int c = 0; c < 4; c++) acc[i][j][c] = 0.f;

    float4 ra[2], rb[2];

    auto ldg = [&](int kt) {
        int k0 = kt * BK;
#pragma unroll
        for (int u = 0; u < 2; u++) {
            int c = tid + u * 256;
            int r = c >> 2, q = c & 3;            // A: 128 rows x 4 float4
            ra[u] = *(const float4*)(X + (size_t)(bm + r) * DM + k0 + q * 4);
            int rr = c >> 5, qb = c & 31;         // B: 16 rows x 32 float4
            rb[u] = *(const float4*)(W + (size_t)(k0 + rr) * DM + bn + qb * 4);
        }
    };
    auto sts = [&](int buf) {
#pragma unroll
        for (int u = 0; u < 2; u++) {
            int c = tid + u * 256;
            int r = c >> 2, q = c & 3;
            As[buf][r][q * 4 + 0] = to_tf32(ra[u].x);
            As[buf][r][q * 4 + 1] = to_tf32(ra[u].y);
            As[buf][r][q * 4 + 2] = to_tf32(ra[u].z);
            As[buf][r][q * 4 + 3] = to_tf32(ra[u].w);
            int rr = c >> 5, qb = c & 31;
            Bs[buf][rr][qb * 4 + 0] = to_tf32(rb[u].x);
            Bs[buf][rr][qb * 4 + 1] = to_tf32(rb[u].y);
            Bs[buf][rr][qb * 4 + 2] = to_tf32(rb[u].z);
            Bs[buf][rr][qb * 4 + 3] = to_tf32(rb[u].w);
        }
    };

    ldg(0);
    sts(0);
    __syncthreads();

    const int NKT = DM / BK;  // 64
    for (int kt = 0; kt < NKT; kt++) {
        int buf = kt & 1;
        if (kt < NKT - 1) ldg(kt + 1);
#pragma unroll
        for (int ks = 0; ks < 2; ks++) {
            int kb = ks * 8;
            uint32_t a[4][4], b[4][2];
#pragma unroll
            for (int mi = 0; mi < 4; mi++) {
                int row = wm + mi * 16 + (lane >> 2);
                int kc = kb + (lane & 3);
                a[mi][0] = As[buf][row][kc];
                a[mi][1] = As[buf][row + 8][kc];
                a[mi][2] = As[buf][row][kc + 4];
                a[mi][3] = As[buf][row + 8][kc + 4];
            }
#pragma unroll
            for (int ni = 0; ni < 4; ni++) {
                int col = wn + ni * 8 + (lane >> 2);
                int kc = kb + (lane & 3);
                b[ni][0] = Bs[buf][kc][col];
                b[ni][1] = Bs[buf][kc + 4][col];
            }
#pragma unroll
            for (int mi = 0; mi < 4; mi++)
#pragma unroll
                for (int ni = 0; ni < 4; ni++)
                    asm volatile(
                        "mma.sync.aligned.m16n8k8.row.col.f32.tf32.tf32.f32 "
                        "{%0,%1,%2,%3}, {%4,%5,%6,%7}, {%8,%9}, {%0,%1,%2,%3};"
                        : "+f"(acc[mi][ni][0]), "+f"(acc[mi][ni][1]),
                          "+f"(acc[mi][ni][2]), "+f"(acc[mi][ni][3])
                        : "r"(a[mi][0]), "r"(a[mi][1]), "r"(a[mi][2]), "r"(a[mi][3]),
                          "r"(b[ni][0]), "r"(b[ni][1]));
        }
        if (kt < NKT - 1) sts(buf ^ 1);
        __syncthreads();
    }

    // Epilogue: bias add, write fp32
#pragma unroll
    for (int mi = 0; mi < 4; mi++) {
        int r0 = bm + wm + mi * 16 + (lane >> 2);
#pragma unroll
        for (int ni = 0; ni < 4; ni++) {
            int col = bn + wn + ni * 8 + 2 * (lane & 3);
            float b0 = bias[col], b1 = bias[col + 1];
            float2 v;
            v.x = acc[mi][ni][0] + b0;
            v.y = acc[mi][ni][1] + b1;
            *(float2*)(out + (size_t)r0 * DM + col) = v;
            v.x = acc[mi][ni][2] + b0;
            v.y = acc[mi][ni][3] + b1;
            *(float2*)(out + (size_t)(r0 + 8) * DM + col) = v;
        }
    }
}

// Per-token: RoPE(Q,K) then 16-head x 16-head attention with softmax over heads.
__global__ __launch_bounds__(128)
void attn_kernel(float* __restrict__ out) {
    __shared__ __align__(16) float q[16][68];
    __shared__ __align__(16) float kk[16][68];
    __shared__ __align__(16) float v[16][68];
    __shared__ float sc[16][16];
    __shared__ float cs[32], sn[32];

    int tok = blockIdx.x;
    int tid = threadIdx.x;
    size_t base = (size_t)tok * DM;
    const float4* Q4 = (const float4*)(g_Q + base);
    const float4* K4 = (const float4*)(g_K + base);
    const float4* V4 = (const float4*)(g_V + base);

#pragma unroll
    for (int u = 0; u < 2; u++) {
        int c = tid + u * 128;          // 256 float4 per matrix
        int r = c >> 4, cc = c & 15;
        *(float4*)&q[r][cc * 4] = Q4[c];
        *(float4*)&kk[r][cc * 4] = K4[c];
        *(float4*)&v[r][cc * 4] = V4[c];
    }
    int s = tok & SEQ_MASK;
    if (tid < 32) {
        cs[tid] = g_cos[s * 32 + tid];
        sn[tid] = g_sin[s * 32 + tid];
    }
    __syncthreads();

    // RoPE in-place on Q and K: 512 pairs each
#pragma unroll
    for (int u = 0; u < 4; u++) {
        int p = tid + u * 128;
        int h = p >> 5, kp = p & 31;
        float c = cs[kp], ss = sn[kp];
        float xe = q[h][2 * kp], xo = q[h][2 * kp + 1];
        q[h][2 * kp]     = xe * c - xo * ss;
        q[h][2 * kp + 1] = xe * ss + xo * c;
        xe = kk[h][2 * kp]; xo = kk[h][2 * kp + 1];
        kk[h][2 * kp]     = xe * c - xo * ss;
        kk[h][2 * kp + 1] = xe * ss + xo * c;
    }
    __syncthreads();

    // Scores: 16x16 head-pair dot products over d=64
#pragma unroll
    for (int u = 0; u < 2; u++) {
        int p = tid + u * 128;
        int i = p >> 4, j = p & 15;
        const float4* qi = (const float4*)&q[i][0];
        const float4* kj = (const float4*)&kk[j][0];
        float a = 0.f;
#pragma unroll
        for (int d = 0; d < 16; d++) {
            float4 a4 = qi[d], b4 = kj[d];
            a += a4.x * b4.x + a4.y * b4.y + a4.z * b4.z + a4.w * b4.w;
        }
        sc[i][j] = a * 0.125f;  // 1/sqrt(64)
    }
    __syncthreads();

    // Softmax over j (16 rows, one thread each)
    if (tid < 16) {
        float m = sc[tid][0];
#pragma unroll
        for (int j = 1; j < 16; j++) m = fmaxf(m, sc[tid][j]);
        float sum = 0.f;
#pragma unroll
        for (int j = 0; j < 16; j++) {
            float e = __expf(sc[tid][j] - m);
            sc[tid][j] = e;
            sum += e;
        }
        float inv = 1.f / sum;
#pragma unroll
        for (int j = 0; j < 16; j++) sc[tid][j] *= inv;
    }
    __syncthreads();

    // out[i][d] = sum_j attn[i][j] * V[j][d]; thread -> (i, 8 d's)
    int i = tid >> 3, d0 = (tid & 7) * 8;
    float4 o0 = {0, 0, 0, 0}, o1 = {0, 0, 0, 0};
#pragma unroll
    for (int j = 0; j < 16; j++) {
        float a = sc[i][j];
        float4 v0 = *(const float4*)&v[j][d0];
        float4 v1 = *(const float4*)&v[j][d0 + 4];
        o0.x += a * v0.x; o0.y += a * v0.y; o0.z += a * v0.z; o0.w += a * v0.w;
        o1.x += a * v1.x; o1.y += a * v1.y; o1.z += a * v1.z; o1.w += a * v1.w;
    }
    *(float4*)(out + base + i * 64 + d0) = o0;
    *(float4*)(out + base + i * 64 + d0 + 4) = o1;
}

extern "C" void kernel_launch(void* const* d_in, const int* in_sizes, int n_in,
                              void* d_out, int out_size) {
    const float* x  = (const float*)d_in[0];
    const float* Wq = (const float*)d_in[1];
    const float* bq = (const float*)d_in[2];
    const float* Wk = (const float*)d_in[3];
    const float* bk = (const float*)d_in[4];
    const float* Wv = (const float*)d_in[5];
    const float* bv = (const float*)d_in[6];
    float* out = (float*)d_out;

    float *qp = nullptr, *kp = nullptr, *vp = nullptr;
    cudaGetSymbolAddress((void**)&qp, g_Q);
    cudaGetSymbolAddress((void**)&kp, g_K);
    cudaGetSymbolAddress((void**)&vp, g_V);

    rope_table_kernel<<<512, 256>>>();

    dim3 grid(DM / BN, NTOK / BM);  // (8, 128)
    gemm_kernel<<<grid, 256>>>(x, Wq, bq, qp);
    gemm_kernel<<<grid, 256>>>(x, Wk, bk, kp);
    gemm_kernel<<<grid, 256>>>(x, Wv, bv, vp);

    attn_kernel<<<NTOK, 128>>>(out);
}